// round 1
// baseline (speedup 1.0000x reference)
#include <cuda_runtime.h>

#define T_DIM 2048
#define B_DIM 64
#define I_DIM 256
#define H_DIM 256
#define M_DIM (T_DIM * B_DIM)   /* 131072 */
#define N_DIM (3 * H_DIM)       /* 768    */
#define K_DIM I_DIM             /* 256    */

// Scratch for gate pre-activations gx[T*B, 3H]  (402 MB)
__device__ float g_gx[(size_t)M_DIM * N_DIM];

// ---------------------------------------------------------------------------
// GEMM: gx[m, n] = sum_k x[m, k] * W[n, k] + b_ih[n]
// x: [M, K] row-major, W: [N, K] row-major (both K-contiguous -> NT SGEMM)
// Block tile 128x128, BK=8, 256 threads, 8x8 micro-tile per thread.
// ---------------------------------------------------------------------------
__global__ __launch_bounds__(256, 2)
void indgru_gemm_kernel(const float* __restrict__ A,
                        const float* __restrict__ W,
                        const float* __restrict__ bias)
{
    __shared__ float As[8][132];   // [k][m], padded to kill STS conflicts
    __shared__ float Bs[8][132];   // [k][n]

    const int tid = threadIdx.x;
    const int bm  = blockIdx.x * 128;
    const int bn  = blockIdx.y * 128;
    const int tx  = tid & 15;       // 0..15  -> n sub-tile
    const int ty  = tid >> 4;       // 0..15  -> m sub-tile

    // global-load mapping: 256 threads load 128 rows x 8 floats (2 float4/row)
    const int lrow  = tid >> 1;     // 0..127
    const int lpart = tid & 1;      // 0 or 1 -> k offset 0 / 4

    const float* Aptr = A + (size_t)(bm + lrow) * K_DIM + lpart * 4;
    const float* Wptr = W + (size_t)(bn + lrow) * K_DIM + lpart * 4;

    float acc[8][8];
#pragma unroll
    for (int i = 0; i < 8; i++)
#pragma unroll
        for (int j = 0; j < 8; j++) acc[i][j] = 0.f;

    float4 aReg = *(const float4*)(Aptr);
    float4 bReg = *(const float4*)(Wptr);

    for (int kt = 0; kt < K_DIM; kt += 8) {
        // stage current tiles to smem
        As[lpart * 4 + 0][lrow] = aReg.x;
        As[lpart * 4 + 1][lrow] = aReg.y;
        As[lpart * 4 + 2][lrow] = aReg.z;
        As[lpart * 4 + 3][lrow] = aReg.w;
        Bs[lpart * 4 + 0][lrow] = bReg.x;
        Bs[lpart * 4 + 1][lrow] = bReg.y;
        Bs[lpart * 4 + 2][lrow] = bReg.z;
        Bs[lpart * 4 + 3][lrow] = bReg.w;
        __syncthreads();

        // prefetch next k-chunk from global while computing
        if (kt + 8 < K_DIM) {
            aReg = *(const float4*)(Aptr + kt + 8);
            bReg = *(const float4*)(Wptr + kt + 8);
        }

#pragma unroll
        for (int kk = 0; kk < 8; kk++) {
            float a[8], b[8];
            *(float4*)(a + 0) = *(const float4*)(&As[kk][ty * 8 + 0]);
            *(float4*)(a + 4) = *(const float4*)(&As[kk][ty * 8 + 4]);
            *(float4*)(b + 0) = *(const float4*)(&Bs[kk][tx * 8 + 0]);
            *(float4*)(b + 4) = *(const float4*)(&Bs[kk][tx * 8 + 4]);
#pragma unroll
            for (int i = 0; i < 8; i++)
#pragma unroll
                for (int j = 0; j < 8; j++)
                    acc[i][j] = fmaf(a[i], b[j], acc[i][j]);
        }
        __syncthreads();
    }

    // bias for this thread's 8 output columns
    float bb[8];
    *(float4*)(bb + 0) = *(const float4*)(bias + bn + tx * 8 + 0);
    *(float4*)(bb + 4) = *(const float4*)(bias + bn + tx * 8 + 4);

#pragma unroll
    for (int i = 0; i < 8; i++) {
        float* Cp = g_gx + (size_t)(bm + ty * 8 + i) * N_DIM + bn + tx * 8;
        float4 v0, v1;
        v0.x = acc[i][0] + bb[0]; v0.y = acc[i][1] + bb[1];
        v0.z = acc[i][2] + bb[2]; v0.w = acc[i][3] + bb[3];
        v1.x = acc[i][4] + bb[4]; v1.y = acc[i][5] + bb[5];
        v1.z = acc[i][6] + bb[6]; v1.w = acc[i][7] + bb[7];
        *(float4*)(Cp + 0) = v0;
        *(float4*)(Cp + 4) = v1;
    }
}

// ---------------------------------------------------------------------------
// Diagonal-recurrence GRU scan. One thread per (b, j): fully independent.
// Software-pipelined gx loads PF steps ahead (DRAM latency cover at low occ).
// ---------------------------------------------------------------------------
#define PF 8

__global__ __launch_bounds__(256)
void indgru_scan_kernel(const float* __restrict__ w_hh,
                        const float* __restrict__ b_hh,
                        float* __restrict__ out)
{
    const int tid = blockIdx.x * blockDim.x + threadIdx.x;   // 0..16383
    const int b = tid >> 8;
    const int j = tid & 255;

    const float whr = w_hh[j];
    const float whz = w_hh[H_DIM + j];
    const float whn = w_hh[2 * H_DIM + j];
    const float bhr = b_hh[j];
    const float bhz = b_hh[H_DIM + j];
    const float bhn = b_hh[2 * H_DIM + j];

    const float* gp = g_gx + (size_t)b * N_DIM + j;   // gx[t=0, b, j]
    const size_t gstride = (size_t)B_DIM * N_DIM;     // 49152

    float br[PF], bz[PF], bn_[PF];
#pragma unroll
    for (int p = 0; p < PF; p++) {
        br[p]  = gp[0];
        bz[p]  = gp[H_DIM];
        bn_[p] = gp[2 * H_DIM];
        gp += gstride;
    }

    float h = 0.f;
    float* op = out + tid;

#define GRU_STEP(xr, xz, xn)                                     \
    do {                                                         \
        float pr = fmaf(whr, h, (xr) + bhr);                     \
        float er = __expf(-pr);                                  \
        float r  = __fdividef(1.f, 1.f + er);                    \
        float pz = fmaf(whz, h, (xz) + bhz);                     \
        float ez = __expf(-pz);                                  \
        float z  = __fdividef(1.f, 1.f + ez);                    \
        float pn = fmaf(r, fmaf(whn, h, bhn), (xn));             \
        float en = __expf(-2.f * pn);                            \
        float nn = __fdividef(1.f - en, 1.f + en);               \
        h = fmaf(z, h - nn, nn);                                 \
    } while (0)

#pragma unroll 8
    for (int t = 0; t < T_DIM - PF; t++) {
        const int s = t & (PF - 1);
        const float xr = br[s], xz = bz[s], xn = bn_[s];
        // prefetch step t+PF into the slot we just consumed
        br[s]  = gp[0];
        bz[s]  = gp[H_DIM];
        bn_[s] = gp[2 * H_DIM];
        gp += gstride;
        GRU_STEP(xr, xz, xn);
        *op = h;
        op += B_DIM * H_DIM;
    }

    // drain the last PF buffered steps (2048 % 8 == 0, so slot == p)
#pragma unroll
    for (int p = 0; p < PF; p++) {
        const float xr = br[p], xz = bz[p], xn = bn_[p];
        GRU_STEP(xr, xz, xn);
        *op = h;
        op += B_DIM * H_DIM;
    }

    // op now points at out + T*B*H + tid  ==  h_n[0, b, j]
    *op = h;
#undef GRU_STEP
}

// ---------------------------------------------------------------------------
extern "C" void kernel_launch(void* const* d_in, const int* in_sizes, int n_in,
                              void* d_out, int out_size)
{
    const float* x    = (const float*)d_in[0];   // [T, B, I]
    const float* W_ih = (const float*)d_in[1];   // [3H, I]
    const float* b_ih = (const float*)d_in[2];   // [3H]
    const float* b_hh = (const float*)d_in[3];   // [3H]
    const float* w_hh = (const float*)d_in[4];   // [3, H]
    float* out = (float*)d_out;                  // [T,B,H] then [1,B,H]

    dim3 grid(M_DIM / 128, N_DIM / 128);         // 1024 x 6
    indgru_gemm_kernel<<<grid, 256>>>(x, W_ih, b_ih);
    indgru_scan_kernel<<<B_DIM * H_DIM / 256, 256>>>(w_hh, b_hh, out);
}

// round 4
// speedup vs baseline: 1.3215x; 1.3215x over previous
#include <cuda_runtime.h>
#include <cuda_bf16.h>
#include <cstdint>

#define T_DIM 2048
#define B_DIM 64
#define I_DIM 256
#define H_DIM 256
#define M_DIM (T_DIM * B_DIM)   /* 131072 */
#define N_DIM (3 * H_DIM)       /* 768    */
#define K_DIM I_DIM             /* 256    */

// ---------------------------------------------------------------------------
// Global scratch (static __device__ arrays: the sanctioned no-alloc path)
// ---------------------------------------------------------------------------
__device__ float         g_gx [(size_t)M_DIM * N_DIM];   // 402 MB gate preacts
__device__ __nv_bfloat16 g_Ahi[(size_t)M_DIM * K_DIM];   // 64 MB
__device__ __nv_bfloat16 g_Alo[(size_t)M_DIM * K_DIM];   // 64 MB
__device__ __nv_bfloat16 g_Bhi[(size_t)N_DIM * K_DIM];
__device__ __nv_bfloat16 g_Blo[(size_t)N_DIM * K_DIM];

// ---------------------------------------------------------------------------
// Baseline-PTX helpers (compute_103-safe: cp.async / ldmatrix / mma.sync only)
// ---------------------------------------------------------------------------
__device__ __forceinline__ uint32_t smem_u32(const void* p) {
    uint32_t a;
    asm("{ .reg .u64 t; cvta.to.shared.u64 t, %1; cvt.u32.u64 %0, t; }"
        : "=r"(a) : "l"(p));
    return a;
}
__device__ __forceinline__ void cp_async16(uint32_t dst, const void* src) {
    asm volatile("cp.async.cg.shared.global [%0], [%1], 16;"
                 :: "r"(dst), "l"(src) : "memory");
}
__device__ __forceinline__ void cp_commit() {
    asm volatile("cp.async.commit_group;" ::: "memory");
}
template<int N> __device__ __forceinline__ void cp_wait() {
    asm volatile("cp.async.wait_group %0;" :: "n"(N) : "memory");
}
__device__ __forceinline__ void ldsm4(uint32_t r[4], uint32_t addr) {
    asm volatile("ldmatrix.sync.aligned.m8n8.x4.shared.b16 {%0,%1,%2,%3}, [%4];"
                 : "=r"(r[0]), "=r"(r[1]), "=r"(r[2]), "=r"(r[3]) : "r"(addr));
}
__device__ __forceinline__ void mma16816(float c[4], const uint32_t a[4],
                                         const uint32_t b0, const uint32_t b1) {
    asm volatile("mma.sync.aligned.m16n8k16.row.col.f32.bf16.bf16.f32 "
                 "{%0,%1,%2,%3}, {%4,%5,%6,%7}, {%8,%9}, {%0,%1,%2,%3};"
                 : "+f"(c[0]), "+f"(c[1]), "+f"(c[2]), "+f"(c[3])
                 : "r"(a[0]), "r"(a[1]), "r"(a[2]), "r"(a[3]), "r"(b0), "r"(b1));
}
__device__ __forceinline__ uint32_t swz(uint32_t b) { return b ^ ((b >> 3) & 0x70); }

// ---------------------------------------------------------------------------
// fp32 -> (bf16 hi, bf16 lo) split conversion.  which=0 -> A arrays, 1 -> B.
// ---------------------------------------------------------------------------
__global__ void split_bf16_kernel(const float4* __restrict__ src, int n4, int which)
{
    int i = blockIdx.x * blockDim.x + threadIdx.x;
    if (i >= n4) return;
    __nv_bfloat16* hi = which ? g_Bhi : g_Ahi;
    __nv_bfloat16* lo = which ? g_Blo : g_Alo;
    float4 v = src[i];
    __nv_bfloat16 h0 = __float2bfloat16(v.x);
    __nv_bfloat16 h1 = __float2bfloat16(v.y);
    __nv_bfloat16 h2 = __float2bfloat16(v.z);
    __nv_bfloat16 h3 = __float2bfloat16(v.w);
    __nv_bfloat16 l0 = __float2bfloat16(v.x - __bfloat162float(h0));
    __nv_bfloat16 l1 = __float2bfloat16(v.y - __bfloat162float(h1));
    __nv_bfloat16 l2 = __float2bfloat16(v.z - __bfloat162float(h2));
    __nv_bfloat16 l3 = __float2bfloat16(v.w - __bfloat162float(h3));
    __nv_bfloat162* ph = (__nv_bfloat162*)(hi + (size_t)i * 4);
    __nv_bfloat162* pl = (__nv_bfloat162*)(lo + (size_t)i * 4);
    ph[0] = __nv_bfloat162(h0, h1); ph[1] = __nv_bfloat162(h2, h3);
    pl[0] = __nv_bfloat162(l0, l1); pl[1] = __nv_bfloat162(l2, l3);
}

// ---------------------------------------------------------------------------
// Split-precision bf16 HMMA GEMM:  gx[m,n] = sum_k x[m,k] W[n,k] + bias[n]
// CTA 128x128, BK=64 (128B rows, SW128 swizzle), 8 warps (warp tile 32x64),
// double-buffered cp.async. Three mma passes: AhBh + AhBl + AlBh (fp32 acc).
// ---------------------------------------------------------------------------
#define BM 128
#define BN 128
#define BK 64
#define NCHUNK (K_DIM / BK)      /* 4 */

#define AHI_OFF 0
#define ALO_OFF 16384
#define BHI_OFF 32768
#define BLO_OFF 49152
#define STAGE_BYTES 65536
#define SMEM_BYTES (2 * STAGE_BYTES)

__global__ __launch_bounds__(256, 1)
void indgru_hmma_gemm(const float* __restrict__ bias)
{
    extern __shared__ char dyn_smem[];
    const uint32_t sb = smem_u32(dyn_smem);

    const int tid = threadIdx.x;
    const int bn  = blockIdx.x * BN;          // 6 N-tiles (x fastest -> A L2 reuse)
    const int bm  = blockIdx.y * BM;          // 1024 M-tiles

    const int warp   = tid >> 5;
    const int lane   = tid & 31;
    const int warp_m = warp >> 1;             // 0..3 -> 32-row slice
    const int warp_n = warp & 1;              // 0..1 -> 64-col slice
    const int r      = lane & 7;
    const int q      = lane >> 3;

    // ---- per-lane ldmatrix row bases (byte offsets within a tile) ----
    // A (m16k16 .x4): row = wm*32 + mt*16 + (q&1)*8 + r ; k-byte off (q>>1)*16
    uint32_t aRow[2], aXor[2];
#pragma unroll
    for (int mt = 0; mt < 2; mt++) {
        int row = warp_m * 32 + mt * 16 + (q & 1) * 8 + r;
        aRow[mt] = row * 128;
        aXor[mt] = (row & 7) * 16;
    }
    const uint32_t aK = (q >> 1) * 16;
    // B (two n8k16 tiles per .x4): row = wn*64 + p*16 + (q>>1)*8 + r ; k off (q&1)*16
    uint32_t bRow[4], bXor[4];
#pragma unroll
    for (int p = 0; p < 4; p++) {
        int row = warp_n * 64 + p * 16 + (q >> 1) * 8 + r;
        bRow[p] = row * 128;
        bXor[p] = (row & 7) * 16;
    }
    const uint32_t bK = (q & 1) * 16;

    float acc[2][8][4];
#pragma unroll
    for (int mt = 0; mt < 2; mt++)
#pragma unroll
        for (int t = 0; t < 8; t++)
#pragma unroll
            for (int e = 0; e < 4; e++) acc[mt][t][e] = 0.f;

    // ---- chunk loader: 16 cp.async(16B) per thread ----
    auto load_chunk = [&](int c) {
        const uint32_t st = sb + (uint32_t)(c & 1) * STAGE_BYTES;
        const int kc = c * BK;
#pragma unroll
        for (int i = 0; i < 4; i++) {
            int cid = tid + i * 256;          // 0..1023
            int row = cid >> 3, c16 = cid & 7;
            uint32_t off = swz((uint32_t)(row * 128 + c16 * 16));
            size_t ga = (size_t)(bm + row) * K_DIM + kc + c16 * 8;
            size_t gb = (size_t)(bn + row) * K_DIM + kc + c16 * 8;
            cp_async16(st + AHI_OFF + off, g_Ahi + ga);
            cp_async16(st + ALO_OFF + off, g_Alo + ga);
            cp_async16(st + BHI_OFF + off, g_Bhi + gb);
            cp_async16(st + BLO_OFF + off, g_Blo + gb);
        }
        cp_commit();
    };

    load_chunk(0);

    for (int c = 0; c < NCHUNK; c++) {
        const uint32_t st = sb + (uint32_t)(c & 1) * STAGE_BYTES;
        if (c + 1 < NCHUNK) { load_chunk(c + 1); cp_wait<1>(); }
        else                { cp_wait<0>(); }
        __syncthreads();

#pragma unroll
        for (int ks = 0; ks < 4; ks++) {      // 4 x k16 inside BK=64
            const uint32_t k2 = ks * 32;      // byte offset of this k16
            uint32_t Ah[2][4], Al[2][4], Bh[4][4], Bl[4][4];
#pragma unroll
            for (int mt = 0; mt < 2; mt++) {
                uint32_t o = aRow[mt] + ((k2 + aK) ^ aXor[mt]);
                ldsm4(Ah[mt], st + AHI_OFF + o);
                ldsm4(Al[mt], st + ALO_OFF + o);
            }
#pragma unroll
            for (int p = 0; p < 4; p++) {
                uint32_t o = bRow[p] + ((k2 + bK) ^ bXor[p]);
                ldsm4(Bh[p], st + BHI_OFF + o);
                ldsm4(Bl[p], st + BLO_OFF + o);
            }
#pragma unroll
            for (int mt = 0; mt < 2; mt++)
#pragma unroll
                for (int p = 0; p < 4; p++) {
                    // .x4 regs: {b0 tile2p, b1 tile2p, b0 tile2p+1, b1 tile2p+1}
                    mma16816(acc[mt][2*p],   Ah[mt], Bh[p][0], Bh[p][1]);
                    mma16816(acc[mt][2*p+1], Ah[mt], Bh[p][2], Bh[p][3]);
                    mma16816(acc[mt][2*p],   Ah[mt], Bl[p][0], Bl[p][1]);
                    mma16816(acc[mt][2*p+1], Ah[mt], Bl[p][2], Bl[p][3]);
                    mma16816(acc[mt][2*p],   Al[mt], Bh[p][0], Bh[p][1]);
                    mma16816(acc[mt][2*p+1], Al[mt], Bh[p][2], Bh[p][3]);
                }
        }
        __syncthreads();
    }

    // ---- epilogue: +bias, store fp32 ----
    const int mrow = bm + warp_m * 32 + (lane >> 2);     // +mt*16, +8 for c2/c3
    const int ncol = bn + warp_n * 64 + (lane & 3) * 2;  // +t*8
#pragma unroll
    for (int t = 0; t < 8; t++) {
        const int n = ncol + t * 8;
        const float b0 = __ldg(bias + n), b1 = __ldg(bias + n + 1);
#pragma unroll
        for (int mt = 0; mt < 2; mt++) {
            float* p0 = g_gx + (size_t)(mrow + mt * 16) * N_DIM + n;
            float* p1 = p0 + 8 * N_DIM;
            *(float2*)p0 = make_float2(acc[mt][t][0] + b0, acc[mt][t][1] + b1);
            *(float2*)p1 = make_float2(acc[mt][t][2] + b0, acc[mt][t][3] + b1);
        }
    }
}

// ---------------------------------------------------------------------------
// Diagonal GRU scan. 64-thread blocks -> 256 blocks spread over all 148 SMs:
// ~1 warp/SMSP, MUFU contention below the ~96-cyc dependent chain.
// ---------------------------------------------------------------------------
#define PF 8

__global__ __launch_bounds__(64)
void indgru_scan_kernel(const float* __restrict__ w_hh,
                        const float* __restrict__ b_hh,
                        float* __restrict__ out)
{
    const int tid = blockIdx.x * blockDim.x + threadIdx.x;   // 0..16383
    const int b = tid >> 8;
    const int j = tid & 255;

    const float whr = w_hh[j];
    const float whz = w_hh[H_DIM + j];
    const float whn = w_hh[2 * H_DIM + j];
    const float bhr = b_hh[j];
    const float bhz = b_hh[H_DIM + j];
    const float bhn = b_hh[2 * H_DIM + j];

    const float* gp = g_gx + (size_t)b * N_DIM + j;
    const size_t gstride = (size_t)B_DIM * N_DIM;

    float br[PF], bz[PF], bn_[PF];
#pragma unroll
    for (int p = 0; p < PF; p++) {
        br[p]  = gp[0];
        bz[p]  = gp[H_DIM];
        bn_[p] = gp[2 * H_DIM];
        gp += gstride;
    }

    float h = 0.f;
    float* op = out + tid;

#define GRU_STEP(xr, xz, xn)                                     \
    do {                                                         \
        float pr = fmaf(whr, h, (xr) + bhr);                     \
        float rr = __fdividef(1.f, 1.f + __expf(-pr));           \
        float pz = fmaf(whz, h, (xz) + bhz);                     \
        float z  = __fdividef(1.f, 1.f + __expf(-pz));           \
        float pn = fmaf(rr, fmaf(whn, h, bhn), (xn));            \
        float s  = __fdividef(1.f, 1.f + __expf(-2.f * pn));     \
        float nn = fmaf(2.f, s, -1.f);   /* tanh(pn) */          \
        h = fmaf(z, h - nn, nn);                                 \
    } while (0)

#pragma unroll 8
    for (int t = 0; t < T_DIM - PF; t++) {
        const int s = t & (PF - 1);
        const float xr = br[s], xz = bz[s], xn = bn_[s];
        br[s]  = gp[0];
        bz[s]  = gp[H_DIM];
        bn_[s] = gp[2 * H_DIM];
        gp += gstride;
        GRU_STEP(xr, xz, xn);
        *op = h;
        op += B_DIM * H_DIM;
    }
#pragma unroll
    for (int p = 0; p < PF; p++) {
        const float xr = br[p], xz = bz[p], xn = bn_[p];
        GRU_STEP(xr, xz, xn);
        *op = h;
        op += B_DIM * H_DIM;
    }
    *op = h;   // h_n[0, b, j]
#undef GRU_STEP
}

// ---------------------------------------------------------------------------
extern "C" void kernel_launch(void* const* d_in, const int* in_sizes, int n_in,
                              void* d_out, int out_size)
{
    const float* x    = (const float*)d_in[0];   // [T, B, I]
    const float* W_ih = (const float*)d_in[1];   // [3H, I]
    const float* b_ih = (const float*)d_in[2];   // [3H]
    const float* b_hh = (const float*)d_in[3];   // [3H]
    const float* w_hh = (const float*)d_in[4];   // [3, H]
    float* out = (float*)d_out;

    cudaFuncSetAttribute(indgru_hmma_gemm,
                         cudaFuncAttributeMaxDynamicSharedMemorySize, SMEM_BYTES);

    // split fp32 -> bf16 hi/lo
    {
        int n4 = M_DIM * K_DIM / 4;
        split_bf16_kernel<<<(n4 + 255) / 256, 256>>>((const float4*)x, n4, 0);
        int w4 = N_DIM * K_DIM / 4;
        split_bf16_kernel<<<(w4 + 255) / 256, 256>>>((const float4*)W_ih, w4, 1);
    }

    dim3 grid(N_DIM / BN, M_DIM / BM);   // (6, 1024)
    indgru_hmma_gemm<<<grid, 256, SMEM_BYTES>>>(b_ih);

    indgru_scan_kernel<<<B_DIM * H_DIM / 64, 64>>>(w_hh, b_hh, out);
}

// round 5
// speedup vs baseline: 2.2237x; 1.6826x over previous
#include <cuda_runtime.h>
#include <cuda_bf16.h>
#include <cstdint>

#define T_DIM 2048
#define B_DIM 64
#define I_DIM 256
#define H_DIM 256
#define M_DIM (T_DIM * B_DIM)   /* 131072 */
#define N_DIM (3 * H_DIM)       /* 768    */
#define K_DIM I_DIM             /* 256    */

// ---------------------------------------------------------------------------
// Global scratch (static __device__ arrays: the sanctioned no-alloc path)
// ---------------------------------------------------------------------------
__device__ float         g_gx [(size_t)M_DIM * N_DIM];   // 402 MB gate preacts
__device__ __nv_bfloat16 g_Ahi[(size_t)M_DIM * K_DIM];   // 64 MB
__device__ __nv_bfloat16 g_Alo[(size_t)M_DIM * K_DIM];   // 64 MB
__device__ __nv_bfloat16 g_Bhi[(size_t)N_DIM * K_DIM];
__device__ __nv_bfloat16 g_Blo[(size_t)N_DIM * K_DIM];

// ---------------------------------------------------------------------------
// Baseline-PTX helpers (compute_103-safe: cp.async / ldmatrix / mma.sync only)
// ---------------------------------------------------------------------------
__device__ __forceinline__ uint32_t smem_u32(const void* p) {
    uint32_t a;
    asm("{ .reg .u64 t; cvta.to.shared.u64 t, %1; cvt.u32.u64 %0, t; }"
        : "=r"(a) : "l"(p));
    return a;
}
__device__ __forceinline__ void cp_async16(uint32_t dst, const void* src) {
    asm volatile("cp.async.cg.shared.global [%0], [%1], 16;"
                 :: "r"(dst), "l"(src) : "memory");
}
__device__ __forceinline__ void cp_commit() {
    asm volatile("cp.async.commit_group;" ::: "memory");
}
template<int N> __device__ __forceinline__ void cp_wait() {
    asm volatile("cp.async.wait_group %0;" :: "n"(N) : "memory");
}
__device__ __forceinline__ void ldsm4(uint32_t r[4], uint32_t addr) {
    asm volatile("ldmatrix.sync.aligned.m8n8.x4.shared.b16 {%0,%1,%2,%3}, [%4];"
                 : "=r"(r[0]), "=r"(r[1]), "=r"(r[2]), "=r"(r[3]) : "r"(addr));
}
__device__ __forceinline__ void mma16816(float c[4], const uint32_t a[4],
                                         const uint32_t b0, const uint32_t b1) {
    asm volatile("mma.sync.aligned.m16n8k16.row.col.f32.bf16.bf16.f32 "
                 "{%0,%1,%2,%3}, {%4,%5,%6,%7}, {%8,%9}, {%0,%1,%2,%3};"
                 : "+f"(c[0]), "+f"(c[1]), "+f"(c[2]), "+f"(c[3])
                 : "r"(a[0]), "r"(a[1]), "r"(a[2]), "r"(a[3]), "r"(b0), "r"(b1));
}
__device__ __forceinline__ float tanh_fast(float x) {
    float y;
    asm("tanh.approx.f32 %0, %1;" : "=f"(y) : "f"(x));
    return y;
}
__device__ __forceinline__ uint32_t swz(uint32_t b) { return b ^ ((b >> 3) & 0x70); }

// ---------------------------------------------------------------------------
// fp32 -> (bf16 hi, bf16 lo) split conversion.  which=0 -> A arrays, 1 -> B.
// ---------------------------------------------------------------------------
__global__ void split_bf16_kernel(const float4* __restrict__ src, int n4, int which)
{
    int i = blockIdx.x * blockDim.x + threadIdx.x;
    if (i >= n4) return;
    __nv_bfloat16* hi = which ? g_Bhi : g_Ahi;
    __nv_bfloat16* lo = which ? g_Blo : g_Alo;
    float4 v = src[i];
    __nv_bfloat16 h0 = __float2bfloat16(v.x);
    __nv_bfloat16 h1 = __float2bfloat16(v.y);
    __nv_bfloat16 h2 = __float2bfloat16(v.z);
    __nv_bfloat16 h3 = __float2bfloat16(v.w);
    __nv_bfloat16 l0 = __float2bfloat16(v.x - __bfloat162float(h0));
    __nv_bfloat16 l1 = __float2bfloat16(v.y - __bfloat162float(h1));
    __nv_bfloat16 l2 = __float2bfloat16(v.z - __bfloat162float(h2));
    __nv_bfloat16 l3 = __float2bfloat16(v.w - __bfloat162float(h3));
    __nv_bfloat162* ph = (__nv_bfloat162*)(hi + (size_t)i * 4);
    __nv_bfloat162* pl = (__nv_bfloat162*)(lo + (size_t)i * 4);
    ph[0] = __nv_bfloat162(h0, h1); ph[1] = __nv_bfloat162(h2, h3);
    pl[0] = __nv_bfloat162(l0, l1); pl[1] = __nv_bfloat162(l2, l3);
}

// ---------------------------------------------------------------------------
// Split-precision bf16 HMMA GEMM:  gx[m,n] = sum_k x[m,k] W[n,k] + bias[n]
// CTA 128x64, BK=64 (128B rows, SW128 swizzle), 8 warps (warp tile 32x32),
// 48KB/stage double-buffered -> 96KB/CTA -> 2 CTAs/SM (16 warps) for latency
// hiding of the HMMA/ldsm streams. Three passes: AhBh + AhBl + AlBh (fp32).
// ---------------------------------------------------------------------------
#define BM 128
#define BN 64
#define BK 64
#define NCHUNK (K_DIM / BK)      /* 4 */

#define AHI_OFF 0
#define ALO_OFF 16384
#define BHI_OFF 32768
#define BLO_OFF 40960
#define STAGE_BYTES 49152        /* 48 KB */
#define SMEM_BYTES (2 * STAGE_BYTES)

__global__ __launch_bounds__(256, 2)
void indgru_hmma_gemm(const float* __restrict__ bias)
{
    extern __shared__ char dyn_smem[];
    const uint32_t sb = smem_u32(dyn_smem);

    const int tid = threadIdx.x;
    const int bn  = blockIdx.x * BN;          // 12 N-tiles (x fastest -> A L2 reuse)
    const int bm  = blockIdx.y * BM;          // 1024 M-tiles

    const int warp   = tid >> 5;
    const int lane   = tid & 31;
    const int warp_m = warp >> 1;             // 0..3 -> 32-row slice
    const int warp_n = warp & 1;              // 0..1 -> 32-col slice
    const int r      = lane & 7;
    const int q      = lane >> 3;

    // ---- per-lane ldmatrix row bases (byte offsets within a tile) ----
    // A (m16k16 .x4): row = wm*32 + mt*16 + (q&1)*8 + r ; k-byte off (q>>1)*16
    uint32_t aRow[2], aXor[2];
#pragma unroll
    for (int mt = 0; mt < 2; mt++) {
        int row = warp_m * 32 + mt * 16 + (q & 1) * 8 + r;
        aRow[mt] = row * 128;
        aXor[mt] = (row & 7) * 16;
    }
    const uint32_t aK = (q >> 1) * 16;
    // B (two n8k16 tiles per .x4): row = wn*32 + p*16 + (q>>1)*8 + r ; k off (q&1)*16
    uint32_t bRow[2], bXor[2];
#pragma unroll
    for (int p = 0; p < 2; p++) {
        int row = warp_n * 32 + p * 16 + (q >> 1) * 8 + r;
        bRow[p] = row * 128;
        bXor[p] = (row & 7) * 16;
    }
    const uint32_t bK = (q & 1) * 16;

    float acc[2][4][4];
#pragma unroll
    for (int mt = 0; mt < 2; mt++)
#pragma unroll
        for (int t = 0; t < 4; t++)
#pragma unroll
            for (int e = 0; e < 4; e++) acc[mt][t][e] = 0.f;

    // ---- chunk loader: 12 cp.async(16B) per thread ----
    auto load_chunk = [&](int c) {
        const uint32_t st = sb + (uint32_t)(c & 1) * STAGE_BYTES;
        const int kc = c * BK;
        // A: 128 rows x 8 chunks, hi+lo
#pragma unroll
        for (int i = 0; i < 4; i++) {
            int cid = tid + i * 256;          // 0..1023
            int row = cid >> 3, c16 = cid & 7;
            uint32_t off = swz((uint32_t)(row * 128 + c16 * 16));
            size_t ga = (size_t)(bm + row) * K_DIM + kc + c16 * 8;
            cp_async16(st + AHI_OFF + off, g_Ahi + ga);
            cp_async16(st + ALO_OFF + off, g_Alo + ga);
        }
        // B: 64 rows x 8 chunks, hi+lo
#pragma unroll
        for (int i = 0; i < 2; i++) {
            int cid = tid + i * 256;          // 0..511
            int row = cid >> 3, c16 = cid & 7;
            uint32_t off = swz((uint32_t)(row * 128 + c16 * 16));
            size_t gb = (size_t)(bn + row) * K_DIM + kc + c16 * 8;
            cp_async16(st + BHI_OFF + off, g_Bhi + gb);
            cp_async16(st + BLO_OFF + off, g_Blo + gb);
        }
        cp_commit();
    };

    load_chunk(0);

    for (int c = 0; c < NCHUNK; c++) {
        const uint32_t st = sb + (uint32_t)(c & 1) * STAGE_BYTES;
        if (c + 1 < NCHUNK) { load_chunk(c + 1); cp_wait<1>(); }
        else                { cp_wait<0>(); }
        __syncthreads();

#pragma unroll
        for (int ks = 0; ks < 4; ks++) {      // 4 x k16 inside BK=64
            const uint32_t k2 = ks * 32;      // byte offset of this k16
            uint32_t Ah[2][4], Al[2][4], Bh[2][4], Bl[2][4];
#pragma unroll
            for (int mt = 0; mt < 2; mt++) {
                uint32_t o = aRow[mt] + ((k2 + aK) ^ aXor[mt]);
                ldsm4(Ah[mt], st + AHI_OFF + o);
                ldsm4(Al[mt], st + ALO_OFF + o);
            }
#pragma unroll
            for (int p = 0; p < 2; p++) {
                uint32_t o = bRow[p] + ((k2 + bK) ^ bXor[p]);
                ldsm4(Bh[p], st + BHI_OFF + o);
                ldsm4(Bl[p], st + BLO_OFF + o);
            }
#pragma unroll
            for (int mt = 0; mt < 2; mt++)
#pragma unroll
                for (int p = 0; p < 2; p++) {
                    // .x4 regs: {b0 tile2p, b1 tile2p, b0 tile2p+1, b1 tile2p+1}
                    mma16816(acc[mt][2*p],   Ah[mt], Bh[p][0], Bh[p][1]);
                    mma16816(acc[mt][2*p+1], Ah[mt], Bh[p][2], Bh[p][3]);
                    mma16816(acc[mt][2*p],   Ah[mt], Bl[p][0], Bl[p][1]);
                    mma16816(acc[mt][2*p+1], Ah[mt], Bl[p][2], Bl[p][3]);
                    mma16816(acc[mt][2*p],   Al[mt], Bh[p][0], Bh[p][1]);
                    mma16816(acc[mt][2*p+1], Al[mt], Bh[p][2], Bh[p][3]);
                }
        }
        __syncthreads();
    }

    // ---- epilogue: +bias, store fp32 ----
    const int mrow = bm + warp_m * 32 + (lane >> 2);     // +mt*16, +8 for c2/c3
    const int ncol = bn + warp_n * 32 + (lane & 3) * 2;  // +t*8
#pragma unroll
    for (int t = 0; t < 4; t++) {
        const int n = ncol + t * 8;
        const float b0 = __ldg(bias + n), b1 = __ldg(bias + n + 1);
#pragma unroll
        for (int mt = 0; mt < 2; mt++) {
            float* p0 = g_gx + (size_t)(mrow + mt * 16) * N_DIM + n;
            float* p1 = p0 + 8 * N_DIM;
            *(float2*)p0 = make_float2(acc[mt][t][0] + b0, acc[mt][t][1] + b1);
            *(float2*)p1 = make_float2(acc[mt][t][2] + b0, acc[mt][t][3] + b1);
        }
    }
}

// ---------------------------------------------------------------------------
// Diagonal GRU scan. 128 blocks x 128 threads (all 4 SMSPs per SM busy),
// PF=16 prefetch depth to bury loaded-DRAM latency, and tanh.approx for all
// gate nonlinearities: sigma(x) = 0.5 + 0.5*tanh(x/2). Chain ~60 cyc/step.
// ---------------------------------------------------------------------------
#define PF 16

__global__ __launch_bounds__(128)
void indgru_scan_kernel(const float* __restrict__ w_hh,
                        const float* __restrict__ b_hh,
                        float* __restrict__ out)
{
    const int tid = blockIdx.x * blockDim.x + threadIdx.x;   // 0..16383
    const int b = tid >> 8;
    const int j = tid & 255;

    const float whr = w_hh[j];
    const float whz = w_hh[H_DIM + j];
    const float whn = w_hh[2 * H_DIM + j];
    const float bhr = b_hh[j];
    const float bhz = b_hh[H_DIM + j];
    const float bhn = b_hh[2 * H_DIM + j];

    const float* gp = g_gx + (size_t)b * N_DIM + j;
    const size_t gstride = (size_t)B_DIM * N_DIM;

    float br[PF], bz[PF], bn_[PF];
#pragma unroll
    for (int p = 0; p < PF; p++) {
        br[p]  = gp[0];
        bz[p]  = gp[H_DIM];
        bn_[p] = gp[2 * H_DIM];
        gp += gstride;
    }

    float h = 0.f;
    float* op = out + tid;

#define GRU_STEP(xr, xz, xn)                                     \
    do {                                                         \
        float pr = fmaf(whr, h, (xr) + bhr);                     \
        float rr = fmaf(0.5f, tanh_fast(0.5f * pr), 0.5f);       \
        float pz = fmaf(whz, h, (xz) + bhz);                     \
        float z  = fmaf(0.5f, tanh_fast(0.5f * pz), 0.5f);       \
        float pn = fmaf(rr, fmaf(whn, h, bhn), (xn));            \
        float nn = tanh_fast(pn);                                \
        h = fmaf(z, h - nn, nn);                                 \
    } while (0)

#pragma unroll 16
    for (int t = 0; t < T_DIM - PF; t++) {
        const int s = t & (PF - 1);
        const float xr = br[s], xz = bz[s], xn = bn_[s];
        br[s]  = gp[0];
        bz[s]  = gp[H_DIM];
        bn_[s] = gp[2 * H_DIM];
        gp += gstride;
        GRU_STEP(xr, xz, xn);
        *op = h;
        op += B_DIM * H_DIM;
    }
#pragma unroll
    for (int p = 0; p < PF; p++) {
        const float xr = br[p], xz = bz[p], xn = bn_[p];
        GRU_STEP(xr, xz, xn);
        *op = h;
        op += B_DIM * H_DIM;
    }
    *op = h;   // h_n[0, b, j]
#undef GRU_STEP
}

// ---------------------------------------------------------------------------
extern "C" void kernel_launch(void* const* d_in, const int* in_sizes, int n_in,
                              void* d_out, int out_size)
{
    const float* x    = (const float*)d_in[0];   // [T, B, I]
    const float* W_ih = (const float*)d_in[1];   // [3H, I]
    const float* b_ih = (const float*)d_in[2];   // [3H]
    const float* b_hh = (const float*)d_in[3];   // [3H]
    const float* w_hh = (const float*)d_in[4];   // [3, H]
    float* out = (float*)d_out;

    cudaFuncSetAttribute(indgru_hmma_gemm,
                         cudaFuncAttributeMaxDynamicSharedMemorySize, SMEM_BYTES);

    // split fp32 -> bf16 hi/lo
    {
        int n4 = M_DIM * K_DIM / 4;
        split_bf16_kernel<<<(n4 + 255) / 256, 256>>>((const float4*)x, n4, 0);
        int w4 = N_DIM * K_DIM / 4;
        split_bf16_kernel<<<(w4 + 255) / 256, 256>>>((const float4*)W_ih, w4, 1);
    }

    dim3 grid(N_DIM / BN, M_DIM / BM);   // (12, 1024)
    indgru_hmma_gemm<<<grid, 256, SMEM_BYTES>>>(b_ih);

    indgru_scan_kernel<<<B_DIM * H_DIM / 128, 128>>>(w_hh, b_hh, out);
}

// round 6
// speedup vs baseline: 4.6594x; 2.0954x over previous
#include <cuda_runtime.h>
#include <cuda_fp16.h>
#include <cstdint>

#define T_DIM 2048
#define B_DIM 64
#define I_DIM 256
#define H_DIM 256
#define M_DIM (T_DIM * B_DIM)   /* 131072 */
#define N_DIM (3 * H_DIM)       /* 768    */
#define K_DIM I_DIM             /* 256    */

// ---------------------------------------------------------------------------
// Global scratch (static __device__ arrays: the sanctioned no-alloc path)
// ---------------------------------------------------------------------------
__device__ __align__(256) float  g_gx[(size_t)M_DIM * N_DIM];  // 402 MB
__device__ __align__(256) __half g_Ah[(size_t)M_DIM * K_DIM];  // 64 MB
__device__ __align__(256) __half g_Bh[(size_t)N_DIM * K_DIM];  // 384 KB

// ---------------------------------------------------------------------------
// Baseline-PTX helpers (compute_103-safe: cp.async / ldmatrix / mma.sync only)
// ---------------------------------------------------------------------------
__device__ __forceinline__ uint32_t smem_u32(const void* p) {
    uint32_t a;
    asm("{ .reg .u64 t; cvta.to.shared.u64 t, %1; cvt.u32.u64 %0, t; }"
        : "=r"(a) : "l"(p));
    return a;
}
__device__ __forceinline__ void cp_async16(uint32_t dst, const void* src) {
    asm volatile("cp.async.cg.shared.global [%0], [%1], 16;"
                 :: "r"(dst), "l"(src) : "memory");
}
__device__ __forceinline__ void cp_commit() {
    asm volatile("cp.async.commit_group;" ::: "memory");
}
template<int N> __device__ __forceinline__ void cp_wait() {
    asm volatile("cp.async.wait_group %0;" :: "n"(N) : "memory");
}
__device__ __forceinline__ void ldsm4(uint32_t r[4], uint32_t addr) {
    asm volatile("ldmatrix.sync.aligned.m8n8.x4.shared.b16 {%0,%1,%2,%3}, [%4];"
                 : "=r"(r[0]), "=r"(r[1]), "=r"(r[2]), "=r"(r[3]) : "r"(addr));
}
__device__ __forceinline__ void mma16816(float c[4], const uint32_t a[4],
                                         const uint32_t b0, const uint32_t b1) {
    asm volatile("mma.sync.aligned.m16n8k16.row.col.f32.f16.f16.f32 "
                 "{%0,%1,%2,%3}, {%4,%5,%6,%7}, {%8,%9}, {%0,%1,%2,%3};"
                 : "+f"(c[0]), "+f"(c[1]), "+f"(c[2]), "+f"(c[3])
                 : "r"(a[0]), "r"(a[1]), "r"(a[2]), "r"(a[3]), "r"(b0), "r"(b1));
}
__device__ __forceinline__ float tanh_fast(float x) {
    float y;
    asm("tanh.approx.f32 %0, %1;" : "=f"(y) : "f"(x));
    return y;
}
__device__ __forceinline__ uint32_t swz(uint32_t b) { return b ^ ((b >> 3) & 0x70); }

// ---------------------------------------------------------------------------
// fp32 -> fp16 conversion.  which=0 -> A (x), 1 -> B (W_ih).
// ---------------------------------------------------------------------------
__global__ void tohalf_kernel(const float4* __restrict__ src, int n4, int which)
{
    int i = blockIdx.x * blockDim.x + threadIdx.x;
    if (i >= n4) return;
    __half* dst = which ? g_Bh : g_Ah;
    float4 v = src[i];
    __half2* p = (__half2*)(dst + (size_t)i * 4);
    p[0] = __floats2half2_rn(v.x, v.y);
    p[1] = __floats2half2_rn(v.z, v.w);
}

// ---------------------------------------------------------------------------
// Single-pass fp16 HMMA GEMM:  gx[m,n] = sum_k x[m,k] W[n,k] + bias[n]
// CTA 128x64, BK=64 (128B rows, SW128 swizzle), 8 warps (warp tile 32x32),
// 24KB/stage, 3-stage cp.async ring, 2 CTAs/SM. fp32 accumulate.
// ---------------------------------------------------------------------------
#define BM 128
#define BN 64
#define BK 64
#define NCHUNK (K_DIM / BK)      /* 4 */

#define AH_OFF 0
#define BH_OFF 16384
#define STAGE_BYTES 24576        /* 24 KB */
#define GEMM_SMEM (3 * STAGE_BYTES)

__global__ __launch_bounds__(256, 2)
void indgru_hmma_gemm(const float* __restrict__ bias)
{
    extern __shared__ char dyn_smem[];
    const uint32_t sb = smem_u32(dyn_smem);

    const int tid = threadIdx.x;
    const int bn  = blockIdx.x * BN;          // 12 N-tiles (x fastest -> A L2 reuse)
    const int bm  = blockIdx.y * BM;          // 1024 M-tiles

    const int warp   = tid >> 5;
    const int lane   = tid & 31;
    const int warp_m = warp >> 1;             // 0..3 -> 32-row slice
    const int warp_n = warp & 1;              // 0..1 -> 32-col slice
    const int r      = lane & 7;
    const int q      = lane >> 3;

    // ---- per-lane ldmatrix row bases (verified in rounds 4/5) ----
    uint32_t aRow[2], aXor[2];
#pragma unroll
    for (int mt = 0; mt < 2; mt++) {
        int row = warp_m * 32 + mt * 16 + (q & 1) * 8 + r;
        aRow[mt] = row * 128;
        aXor[mt] = (row & 7) * 16;
    }
    const uint32_t aK = (q >> 1) * 16;
    uint32_t bRow[2], bXor[2];
#pragma unroll
    for (int p = 0; p < 2; p++) {
        int row = warp_n * 32 + p * 16 + (q >> 1) * 8 + r;
        bRow[p] = row * 128;
        bXor[p] = (row & 7) * 16;
    }
    const uint32_t bK = (q & 1) * 16;

    float acc[2][4][4];
#pragma unroll
    for (int mt = 0; mt < 2; mt++)
#pragma unroll
        for (int t = 0; t < 4; t++)
#pragma unroll
            for (int e = 0; e < 4; e++) acc[mt][t][e] = 0.f;

    // ---- chunk loader: 6 cp.async(16B) per thread ----
    auto load_chunk = [&](int c) {
        const uint32_t st = sb + (uint32_t)(c % 3) * STAGE_BYTES;
        const int kc = c * BK;
#pragma unroll
        for (int i = 0; i < 4; i++) {         // A: 128 rows x 8 x 16B
            int cid = tid + i * 256;
            int row = cid >> 3, c16 = cid & 7;
            uint32_t off = swz((uint32_t)(row * 128 + c16 * 16));
            cp_async16(st + AH_OFF + off,
                       g_Ah + (size_t)(bm + row) * K_DIM + kc + c16 * 8);
        }
#pragma unroll
        for (int i = 0; i < 2; i++) {         // B: 64 rows x 8 x 16B
            int cid = tid + i * 256;
            int row = cid >> 3, c16 = cid & 7;
            uint32_t off = swz((uint32_t)(row * 128 + c16 * 16));
            cp_async16(st + BH_OFF + off,
                       g_Bh + (size_t)(bn + row) * K_DIM + kc + c16 * 8);
        }
        cp_commit();
    };

    auto compute = [&](int c) {
        const uint32_t st = sb + (uint32_t)(c % 3) * STAGE_BYTES;
#pragma unroll
        for (int ks = 0; ks < 4; ks++) {
            const uint32_t k2 = ks * 32;
            uint32_t Ah[2][4], Bh[2][4];
#pragma unroll
            for (int mt = 0; mt < 2; mt++)
                ldsm4(Ah[mt], st + AH_OFF + aRow[mt] + ((k2 + aK) ^ aXor[mt]));
#pragma unroll
            for (int p = 0; p < 2; p++)
                ldsm4(Bh[p], st + BH_OFF + bRow[p] + ((k2 + bK) ^ bXor[p]));
#pragma unroll
            for (int mt = 0; mt < 2; mt++)
#pragma unroll
                for (int p = 0; p < 2; p++) {
                    mma16816(acc[mt][2*p],   Ah[mt], Bh[p][0], Bh[p][1]);
                    mma16816(acc[mt][2*p+1], Ah[mt], Bh[p][2], Bh[p][3]);
                }
        }
    };

    load_chunk(0); load_chunk(1); load_chunk(2);
    cp_wait<2>(); __syncthreads();
    compute(0);
    __syncthreads();
    load_chunk(3);
    cp_wait<2>(); __syncthreads();
    compute(1);
    cp_wait<1>(); __syncthreads();
    compute(2);
    cp_wait<0>(); __syncthreads();
    compute(3);

    // ---- epilogue: +bias, store fp32 (verified in rounds 4/5) ----
    const int mrow = bm + warp_m * 32 + (lane >> 2);
    const int ncol = bn + warp_n * 32 + (lane & 3) * 2;
#pragma unroll
    for (int t = 0; t < 4; t++) {
        const int n = ncol + t * 8;
        const float b0 = __ldg(bias + n), b1 = __ldg(bias + n + 1);
#pragma unroll
        for (int mt = 0; mt < 2; mt++) {
            float* p0 = g_gx + (size_t)(mrow + mt * 16) * N_DIM + n;
            float* p1 = p0 + 8 * N_DIM;
            *(float2*)p0 = make_float2(acc[mt][t][0] + b0, acc[mt][t][1] + b1);
            *(float2*)p1 = make_float2(acc[mt][t][2] + b0, acc[mt][t][3] + b1);
        }
    }
}

// ---------------------------------------------------------------------------
// Diagonal GRU scan with a cp.async smem ring.
// 128 blocks x 128 threads; block handles (b = blk/2, j in [128*(blk&1), +128)).
// Ring: 8 stages x 8 steps x (3 gates x 128 j) floats = 96 KB. cp.async runs
// 56 steps (~4000 cyc) ahead -> DRAM latency fully hidden; inner loop is
// conflict-free 4B LDS + the ~55-cyc dependent GRU chain.
// ---------------------------------------------------------------------------
#define CS 8                       /* steps per chunk  */
#define NS 8                       /* ring stages      */
#define NCH (T_DIM / CS)           /* 256 chunks       */
#define CHUNK_FLOATS (CS * 3 * 128)
#define SCAN_SMEM (NS * CHUNK_FLOATS * 4)   /* 98304 */

__global__ __launch_bounds__(128)
void indgru_scan_kernel(const float* __restrict__ w_hh,
                        const float* __restrict__ b_hh,
                        float* __restrict__ out)
{
    extern __shared__ float ring[];          // [NS][CS][3][128]
    const uint32_t ring_b = smem_u32(ring);

    const int tx    = threadIdx.x;
    const int warp  = tx >> 5;
    const int lane  = tx & 31;
    const int b     = blockIdx.x >> 1;
    const int jbase = (blockIdx.x & 1) * 128;
    const int j     = jbase + tx;

    const float whr = w_hh[j];
    const float whz = w_hh[H_DIM + j];
    const float whn = w_hh[2 * H_DIM + j];
    const float bhr = b_hh[j];
    const float bhz = b_hh[H_DIM + j];
    const float bhn = b_hh[2 * H_DIM + j];

    const float* gbase = g_gx + (size_t)b * N_DIM + jbase;

    // per-chunk loader: 24 rows of (step,gate), 512B coalesced per row
    auto load_chunk = [&](int ci) {
        if (ci < NCH) {
            const float* cb = gbase + (size_t)ci * CS * (B_DIM * N_DIM);
            const uint32_t d0 = ring_b + (uint32_t)(ci & (NS - 1)) * (CHUNK_FLOATS * 4);
#pragma unroll
            for (int k = 0; k < 6; k++) {
                int row  = warp * 6 + k;      // 0..23
                int step = row / 3, gate = row % 3;
                cp_async16(d0 + (uint32_t)(((step * 3 + gate) * 128 + lane * 4) * 4),
                           cb + (size_t)step * (B_DIM * N_DIM) + gate * H_DIM + lane * 4);
            }
        }
        cp_commit();                          // empty group past the end keeps counts uniform
    };

#pragma unroll
    for (int c = 0; c < NS - 1; c++) load_chunk(c);   // 7 chunks in flight

    float h = 0.f;
    float* op = out + b * H_DIM + j;

#define GRU_STEP(xr, xz, xn)                                     \
    do {                                                         \
        float pr = fmaf(whr, h, (xr) + bhr);                     \
        float rr = fmaf(0.5f, tanh_fast(0.5f * pr), 0.5f);       \
        float pz = fmaf(whz, h, (xz) + bhz);                     \
        float z  = fmaf(0.5f, tanh_fast(0.5f * pz), 0.5f);       \
        float pn = fmaf(rr, fmaf(whn, h, bhn), (xn));            \
        float nn = tanh_fast(pn);                                \
        h = fmaf(z, h - nn, nn);                                 \
    } while (0)

    for (int ci = 0; ci < NCH; ci++) {
        cp_wait<NS - 2>();                    // chunk ci arrived (all groups <= ci done)
        __syncthreads();                      // cross-thread visibility
        const float* st = ring + (ci & (NS - 1)) * CHUNK_FLOATS;
#pragma unroll
        for (int s = 0; s < CS; s++) {
            const float xr = st[(s * 3 + 0) * 128 + tx];
            const float xz = st[(s * 3 + 1) * 128 + tx];
            const float xn = st[(s * 3 + 2) * 128 + tx];
            GRU_STEP(xr, xz, xn);
            *op = h;
            op += B_DIM * H_DIM;
        }
        load_chunk(ci + NS - 1);              // refills stage consumed at ci-1 (safe)
    }
    *op = h;                                  // h_n[0, b, j]
#undef GRU_STEP
}

// ---------------------------------------------------------------------------
extern "C" void kernel_launch(void* const* d_in, const int* in_sizes, int n_in,
                              void* d_out, int out_size)
{
    const float* x    = (const float*)d_in[0];   // [T, B, I]
    const float* W_ih = (const float*)d_in[1];   // [3H, I]
    const float* b_ih = (const float*)d_in[2];   // [3H]
    const float* b_hh = (const float*)d_in[3];   // [3H]
    const float* w_hh = (const float*)d_in[4];   // [3, H]
    float* out = (float*)d_out;

    cudaFuncSetAttribute(indgru_hmma_gemm,
                         cudaFuncAttributeMaxDynamicSharedMemorySize, GEMM_SMEM);
    cudaFuncSetAttribute(indgru_scan_kernel,
                         cudaFuncAttributeMaxDynamicSharedMemorySize, SCAN_SMEM);

    {   // fp32 -> fp16
        int n4 = M_DIM * K_DIM / 4;
        tohalf_kernel<<<(n4 + 255) / 256, 256>>>((const float4*)x, n4, 0);
        int w4 = N_DIM * K_DIM / 4;
        tohalf_kernel<<<(w4 + 255) / 256, 256>>>((const float4*)W_ih, w4, 1);
    }

    dim3 grid(N_DIM / BN, M_DIM / BM);   // (12, 1024)
    indgru_hmma_gemm<<<grid, 256, GEMM_SMEM>>>(b_ih);

    indgru_scan_kernel<<<2 * B_DIM, 128, SCAN_SMEM>>>(w_hh, b_hh, out);
}

// round 10
// speedup vs baseline: 4.9808x; 1.0690x over previous
#include <cuda_runtime.h>
#include <cuda_fp16.h>
#include <cstdint>

#define T_DIM 2048
#define B_DIM 64
#define I_DIM 256
#define H_DIM 256
#define M_DIM (T_DIM * B_DIM)   /* 131072 */
#define N_DIM (3 * H_DIM)       /* 768    */
#define K_DIM I_DIM             /* 256    */

// ---------------------------------------------------------------------------
// Global scratch (static __device__ arrays: the sanctioned no-alloc path)
// ---------------------------------------------------------------------------
__device__ __align__(256) __half g_gxh[(size_t)M_DIM * N_DIM]; // 201 MB fp16 preacts
__device__ __align__(256) __half g_Ah [(size_t)M_DIM * K_DIM]; // 64 MB
__device__ __align__(256) __half g_Bh [(size_t)N_DIM * K_DIM]; // 384 KB

// ---------------------------------------------------------------------------
// Baseline-PTX helpers (compute_103-safe: cp.async / ldmatrix / mma.sync only)
// ---------------------------------------------------------------------------
__device__ __forceinline__ uint32_t smem_u32(const void* p) {
    uint32_t a;
    asm("{ .reg .u64 t; cvta.to.shared.u64 t, %1; cvt.u32.u64 %0, t; }"
        : "=r"(a) : "l"(p));
    return a;
}
__device__ __forceinline__ void cp_async16(uint32_t dst, const void* src) {
    asm volatile("cp.async.cg.shared.global [%0], [%1], 16;"
                 :: "r"(dst), "l"(src) : "memory");
}
__device__ __forceinline__ void cp_commit() {
    asm volatile("cp.async.commit_group;" ::: "memory");
}
template<int N> __device__ __forceinline__ void cp_wait() {
    asm volatile("cp.async.wait_group %0;" :: "n"(N) : "memory");
}
__device__ __forceinline__ void ldsm4(uint32_t r[4], uint32_t addr) {
    asm volatile("ldmatrix.sync.aligned.m8n8.x4.shared.b16 {%0,%1,%2,%3}, [%4];"
                 : "=r"(r[0]), "=r"(r[1]), "=r"(r[2]), "=r"(r[3]) : "r"(addr));
}
__device__ __forceinline__ void mma16816(float c[4], const uint32_t a[4],
                                         const uint32_t b0, const uint32_t b1) {
    asm volatile("mma.sync.aligned.m16n8k16.row.col.f32.f16.f16.f32 "
                 "{%0,%1,%2,%3}, {%4,%5,%6,%7}, {%8,%9}, {%0,%1,%2,%3};"
                 : "+f"(c[0]), "+f"(c[1]), "+f"(c[2]), "+f"(c[3])
                 : "r"(a[0]), "r"(a[1]), "r"(a[2]), "r"(a[3]), "r"(b0), "r"(b1));
}
__device__ __forceinline__ float tanh_fast(float x) {
    float y;
    asm("tanh.approx.f32 %0, %1;" : "=f"(y) : "f"(x));
    return y;
}
__device__ __forceinline__ uint32_t swz(uint32_t b) { return b ^ ((b >> 3) & 0x70); }

// ---------------------------------------------------------------------------
// fp32 -> fp16 conversion.  which=0 -> A (x), 1 -> B (W_ih).
// ---------------------------------------------------------------------------
__global__ void tohalf_kernel(const float4* __restrict__ src, int n4, int which)
{
    int i = blockIdx.x * blockDim.x + threadIdx.x;
    if (i >= n4) return;
    __half* dst = which ? g_Bh : g_Ah;
    float4 v = src[i];
    __half2* p = (__half2*)(dst + (size_t)i * 4);
    p[0] = __floats2half2_rn(v.x, v.y);
    p[1] = __floats2half2_rn(v.z, v.w);
}

// ---------------------------------------------------------------------------
// Single-pass fp16 HMMA GEMM:  gx[m,n] = sum_k x[m,k] W[n,k] + bias[n]
// CTA 128x128, BK=64 (128B rows, SW128 swizzle), 8 warps (warp tile 32x64),
// 32KB/stage, 3-stage cp.async ring, 2 CTAs/SM. fp32 accumulate, fp16 out.
// (A/B fragment mapping verified in round 4.)
// ---------------------------------------------------------------------------
#define BM 128
#define BN 128
#define BK 64
#define NCHUNK (K_DIM / BK)      /* 4 */

#define AH_OFF 0
#define BH_OFF 16384
#define STAGE_BYTES 32768        /* 32 KB */
#define GEMM_SMEM (3 * STAGE_BYTES)

__global__ __launch_bounds__(256, 2)
void indgru_hmma_gemm(const float* __restrict__ bias)
{
    extern __shared__ char dyn_smem[];
    const uint32_t sb = smem_u32(dyn_smem);

    const int tid = threadIdx.x;
    const int bn  = blockIdx.x * BN;          // 6 N-tiles (x fastest -> A L2 reuse)
    const int bm  = blockIdx.y * BM;          // 1024 M-tiles

    const int warp   = tid >> 5;
    const int lane   = tid & 31;
    const int warp_m = warp >> 1;             // 0..3 -> 32-row slice
    const int warp_n = warp & 1;              // 0..1 -> 64-col slice
    const int r      = lane & 7;
    const int q      = lane >> 3;

    // ---- per-lane ldmatrix row bases (verified round 4) ----
    uint32_t aRow[2], aXor[2];
#pragma unroll
    for (int mt = 0; mt < 2; mt++) {
        int row = warp_m * 32 + mt * 16 + (q & 1) * 8 + r;
        aRow[mt] = row * 128;
        aXor[mt] = (row & 7) * 16;
    }
    const uint32_t aK = (q >> 1) * 16;
    uint32_t bRow[4], bXor[4];
#pragma unroll
    for (int p = 0; p < 4; p++) {
        int row = warp_n * 64 + p * 16 + (q >> 1) * 8 + r;
        bRow[p] = row * 128;
        bXor[p] = (row & 7) * 16;
    }
    const uint32_t bK = (q & 1) * 16;

    float acc[2][8][4];
#pragma unroll
    for (int mt = 0; mt < 2; mt++)
#pragma unroll
        for (int t = 0; t < 8; t++)
#pragma unroll
            for (int e = 0; e < 4; e++) acc[mt][t][e] = 0.f;

    // ---- chunk loader: 8 cp.async(16B) per thread ----
    auto load_chunk = [&](int c) {
        const uint32_t st = sb + (uint32_t)(c % 3) * STAGE_BYTES;
        const int kc = c * BK;
#pragma unroll
        for (int i = 0; i < 4; i++) {         // A: 128 rows x 8 x 16B
            int cid = tid + i * 256;
            int row = cid >> 3, c16 = cid & 7;
            uint32_t off = swz((uint32_t)(row * 128 + c16 * 16));
            cp_async16(st + AH_OFF + off,
                       g_Ah + (size_t)(bm + row) * K_DIM + kc + c16 * 8);
        }
#pragma unroll
        for (int i = 0; i < 4; i++) {         // B: 128 rows x 8 x 16B
            int cid = tid + i * 256;
            int row = cid >> 3, c16 = cid & 7;
            uint32_t off = swz((uint32_t)(row * 128 + c16 * 16));
            cp_async16(st + BH_OFF + off,
                       g_Bh + (size_t)(bn + row) * K_DIM + kc + c16 * 8);
        }
        cp_commit();
    };

    auto compute = [&](int c) {
        const uint32_t st = sb + (uint32_t)(c % 3) * STAGE_BYTES;
#pragma unroll
        for (int ks = 0; ks < 4; ks++) {
            const uint32_t k2 = ks * 32;
            uint32_t Ah[2][4], Bh[4][4];
#pragma unroll
            for (int mt = 0; mt < 2; mt++)
                ldsm4(Ah[mt], st + AH_OFF + aRow[mt] + ((k2 + aK) ^ aXor[mt]));
#pragma unroll
            for (int p = 0; p < 4; p++)
                ldsm4(Bh[p], st + BH_OFF + bRow[p] + ((k2 + bK) ^ bXor[p]));
#pragma unroll
            for (int mt = 0; mt < 2; mt++)
#pragma unroll
                for (int p = 0; p < 4; p++) {
                    mma16816(acc[mt][2*p],   Ah[mt], Bh[p][0], Bh[p][1]);
                    mma16816(acc[mt][2*p+1], Ah[mt], Bh[p][2], Bh[p][3]);
                }
        }
    };

    load_chunk(0); load_chunk(1); load_chunk(2);
    cp_wait<2>(); __syncthreads();
    compute(0);
    __syncthreads();
    load_chunk(3);
    cp_wait<2>(); __syncthreads();
    compute(1);
    cp_wait<1>(); __syncthreads();
    compute(2);
    cp_wait<0>(); __syncthreads();
    compute(3);

    // ---- epilogue: +bias, convert fp16, store ----
    const int mrow = bm + warp_m * 32 + (lane >> 2);
    const int ncol = bn + warp_n * 64 + (lane & 3) * 2;
#pragma unroll
    for (int t = 0; t < 8; t++) {
        const int n = ncol + t * 8;
        const float b0 = __ldg(bias + n), b1 = __ldg(bias + n + 1);
#pragma unroll
        for (int mt = 0; mt < 2; mt++) {
            __half* p0 = g_gxh + (size_t)(mrow + mt * 16) * N_DIM + n;
            __half* p1 = p0 + 8 * N_DIM;
            *(__half2*)p0 = __floats2half2_rn(acc[mt][t][0] + b0, acc[mt][t][1] + b1);
            *(__half2*)p1 = __floats2half2_rn(acc[mt][t][2] + b0, acc[mt][t][3] + b1);
        }
    }
}

// ---------------------------------------------------------------------------
// Diagonal GRU scan with fp16 cp.async smem ring.
// 256 blocks x 64 threads; block handles (b = blk/4, j in [64*(blk&3), +64)).
// Ring: 8 stages x 8 steps x (3 gates x 64 halfs) = 24 KB. 56 steps of
// prefetch in flight -> DRAM latency buried; inner loop: LDS.U16 + ~55-cyc
// dependent GRU chain (tanh.approx).
// ---------------------------------------------------------------------------
#define CS 8                       /* steps per chunk  */
#define NS 8                       /* ring stages      */
#define NCH (T_DIM / CS)           /* 256 chunks       */
#define JW 64                      /* j-width per block */
#define CHUNK_HALFS (CS * 3 * JW)  /* 1536 */
#define SCAN_SMEM (NS * CHUNK_HALFS * 2)    /* 24576 */

__global__ __launch_bounds__(64)
void indgru_scan_kernel(const float* __restrict__ w_hh,
                        const float* __restrict__ b_hh,
                        float* __restrict__ out)
{
    extern __shared__ __half ringh[];        // [NS][CS][3][JW]
    const uint32_t ring_b = smem_u32(ringh);

    const int tx    = threadIdx.x;           // 0..63
    const int b     = blockIdx.x >> 2;
    const int jbase = (blockIdx.x & 3) * JW;
    const int j     = jbase + tx;

    const float whr = w_hh[j];
    const float whz = w_hh[H_DIM + j];
    const float whn = w_hh[2 * H_DIM + j];
    const float bhr = b_hh[j];
    const float bhz = b_hh[H_DIM + j];
    const float bhn = b_hh[2 * H_DIM + j];

    const __half* gbase = g_gxh + (size_t)b * N_DIM + jbase;

    // per-chunk loader: 24 rows of (step,gate) x 128B; 192 16B ops, 3/thread
    auto load_chunk = [&](int ci) {
        if (ci < NCH) {
            const __half* cb = gbase + (size_t)ci * CS * (B_DIM * N_DIM);
            const uint32_t d0 = ring_b + (uint32_t)(ci & (NS - 1)) * (CHUNK_HALFS * 2);
#pragma unroll
            for (int i = 0; i < 3; i++) {
                int cid  = tx + i * 64;       // 0..191
                int row  = cid >> 3;          // 0..23 = step*3+gate
                int sub  = cid & 7;           // 16B sub-chunk (8 halfs)
                int step = row / 3, gate = row % 3;
                cp_async16(d0 + (uint32_t)(row * 128 + sub * 16),
                           cb + (size_t)step * (B_DIM * N_DIM) + gate * H_DIM + sub * 8);
            }
        }
        cp_commit();                          // uniform group count past the end
    };

#pragma unroll
    for (int c = 0; c < NS - 1; c++) load_chunk(c);   // 7 chunks in flight

    float h = 0.f;
    float* op = out + b * H_DIM + j;

#define GRU_STEP(xr, xz, xn)                                     \
    do {                                                         \
        float pr = fmaf(whr, h, (xr) + bhr);                     \
        float rr = fmaf(0.5f, tanh_fast(0.5f * pr), 0.5f);       \
        float pz = fmaf(whz, h, (xz) + bhz);                     \
        float z  = fmaf(0.5f, tanh_fast(0.5f * pz), 0.5f);       \
        float pn = fmaf(rr, fmaf(whn, h, bhn), (xn));            \
        float nn = tanh_fast(pn);                                \
        h = fmaf(z, h - nn, nn);                                 \
    } while (0)

    for (int ci = 0; ci < NCH; ci++) {
        cp_wait<NS - 2>();                    // chunk ci fully arrived
        __syncthreads();
        const __half* st = ringh + (ci & (NS - 1)) * CHUNK_HALFS;
#pragma unroll
        for (int s = 0; s < CS; s++) {
            const float xr = __half2float(st[(s * 3 + 0) * JW + tx]);
            const float xz = __half2float(st[(s * 3 + 1) * JW + tx]);
            const float xn = __half2float(st[(s * 3 + 2) * JW + tx]);
            GRU_STEP(xr, xz, xn);
            *op = h;
            op += B_DIM * H_DIM;
        }
        load_chunk(ci + NS - 1);
    }
    *op = h;                                  // h_n[0, b, j]
#undef GRU_STEP
}

// ---------------------------------------------------------------------------
extern "C" void kernel_launch(void* const* d_in, const int* in_sizes, int n_in,
                              void* d_out, int out_size)
{
    const float* x    = (const float*)d_in[0];   // [T, B, I]
    const float* W_ih = (const float*)d_in[1];   // [3H, I]
    const float* b_ih = (const float*)d_in[2];   // [3H]
    const float* b_hh = (const float*)d_in[3];   // [3H]
    const float* w_hh = (const float*)d_in[4];   // [3, H]
    float* out = (float*)d_out;

    cudaFuncSetAttribute(indgru_hmma_gemm,
                         cudaFuncAttributeMaxDynamicSharedMemorySize, GEMM_SMEM);
    cudaFuncSetAttribute(indgru_scan_kernel,
                         cudaFuncAttributeMaxDynamicSharedMemorySize, SCAN_SMEM);

    {   // fp32 -> fp16
        int n4 = M_DIM * K_DIM / 4;
        tohalf_kernel<<<(n4 + 255) / 256, 256>>>((const float4*)x, n4, 0);
        int w4 = N_DIM * K_DIM / 4;
        tohalf_kernel<<<(w4 + 255) / 256, 256>>>((const float4*)W_ih, w4, 1);
    }

    dim3 grid(N_DIM / BN, M_DIM / BM);   // (6, 1024)
    indgru_hmma_gemm<<<grid, 256, GEMM_SMEM>>>(b_ih);

    indgru_scan_kernel<<<4 * B_DIM, 64, SCAN_SMEM>>>(w_hh, b_hh, out);
}